// round 1
// baseline (speedup 1.0000x reference)
#include <cuda_runtime.h>

#define VOCABSZ 50000
#define EMSIZE  300
#define NBINS   5
#define BB      32
#define QQ      16
#define DD      10
#define LL      1000

typedef unsigned long long ull;

// ---------------- device scratch (no allocations allowed) ----------------
__device__ float g_invnorm[VOCABSZ];
__device__ float g_qn[BB * EMSIZE * QQ];   // [b][e][q], pre-normalized query embeddings
__device__ float g_tbl[BB * QQ * NBINS];   // tw[b,q] * w1[n]
__device__ float g_logits[BB * QQ];
__device__ float g_c0[BB];
__device__ float g_c1;

// ---------------- helpers ----------------
__device__ __forceinline__ ull fma2(ull a, ull b, ull c) {
    ull d;
    asm("fma.rn.f32x2 %0, %1, %2, %3;" : "=l"(d) : "l"(a), "l"(b), "l"(c));
    return d;
}
__device__ __forceinline__ ull dup2(float x) {
    ull d;
    asm("mov.b64 %0, {%1, %1};" : "=l"(d) : "r"(__float_as_uint(x)));
    return d;
}
__device__ __forceinline__ void unpack2(ull p, float& lo, float& hi) {
    unsigned a, b;
    asm("mov.b64 {%0, %1}, %2;" : "=r"(a), "=r"(b) : "l"(p));
    lo = __uint_as_float(a);
    hi = __uint_as_float(b);
}
__device__ __forceinline__ float warp_sum(float v) {
#pragma unroll
    for (int o = 16; o > 0; o >>= 1) v += __shfl_xor_sync(0xffffffffu, v, o);
    return v;
}

// bin semantics from reference: [-1,-.5) [-0.5,0) [0,.5) [.5,1) and {==1.0};
// out-of-range values fall into no bin (contribute 0).
__device__ __forceinline__ float contrib(float v, const float* t5) {
    if (v < -1.0f) return 0.0f;
    if (v < -0.5f) return t5[0];
    if (v <  0.0f) return t5[1];
    if (v <  0.5f) return t5[2];
    if (v <  1.0f) return t5[3];
    return (v == 1.0f) ? t5[4] : 0.0f;
}

// ---------------- K0: per-vocab inverse norms ----------------
__global__ void k_vocab_norms(const float* __restrict__ emb) {
    int w = (blockIdx.x * blockDim.x + threadIdx.x) >> 5;
    int lane = threadIdx.x & 31;
    if (w >= VOCABSZ) return;
    const float* row = emb + (size_t)w * EMSIZE;
    float s = 0.0f;
    for (int e = lane; e < EMSIZE; e += 32) {
        float v = row[e];
        s += v * v;
    }
    s = warp_sum(s);
    if (lane == 0) g_invnorm[w] = 1.0f / sqrtf(s);
}

// ---------------- K1: gather + normalize query embeddings, gate logits ----------------
__global__ void k_query_prep(const int* __restrict__ queries, const float* __restrict__ emb,
                             const float* __restrict__ gate_w, const float* __restrict__ gate_b) {
    int w = (blockIdx.x * blockDim.x + threadIdx.x) >> 5;  // (b,q) index 0..511
    int lane = threadIdx.x & 31;
    if (w >= BB * QQ) return;
    int b = w >> 4, q = w & 15;
    int tok = queries[w];
    const float* row = emb + (size_t)tok * EMSIZE;
    float vv[10];
    float s = 0.0f, g = 0.0f;
    int n = 0;
    for (int e = lane; e < EMSIZE; e += 32) {
        float v = row[e];
        vv[n++] = v;
        s += v * v;
        g += v * gate_w[e];
    }
    s = warp_sum(s);
    g = warp_sum(g);
    float invn = 1.0f / sqrtf(s);
    if (lane == 0) g_logits[w] = g + gate_b[0];
    n = 0;
    for (int e = lane; e < EMSIZE; e += 32) {
        g_qn[b * (EMSIZE * QQ) + e * QQ + q] = vv[n++] * invn;  // transposed [e][q]
    }
}

// ---------------- K2: softmax over query terms + fused scalar constants ----------------
__global__ void k_softmax(const float* __restrict__ w1, const float* __restrict__ b1,
                          const float* __restrict__ w2, const float* __restrict__ b2,
                          const float* __restrict__ ow, const float* __restrict__ ob) {
    int t = threadIdx.x;  // 512 threads: b = t/16, q = t%16
    int b = t >> 4, q = t & 15;
    float logit = g_logits[t];
    float m = logit;
#pragma unroll
    for (int o = 8; o > 0; o >>= 1) m = fmaxf(m, __shfl_xor_sync(0xffffffffu, m, o, 16));
    float e = expf(logit - m);
    float sum = e;
#pragma unroll
    for (int o = 8; o > 0; o >>= 1) sum += __shfl_xor_sync(0xffffffffu, sum, o, 16);
    float tw = e / sum;
    float tws = tw;
#pragma unroll
    for (int o = 8; o > 0; o >>= 1) tws += __shfl_xor_sync(0xffffffffu, tws, o, 16);
#pragma unroll
    for (int n = 0; n < NBINS; n++) g_tbl[(b * QQ + q) * NBINS + n] = tw * w1[n];
    if (q == 0) g_c0[b] = ob[0] + ow[0] * (w2[0] * b1[0] + b2[0]) * tws;
    if (t == 0) g_c1 = ow[0] * w2[0];
}

// ---------------- K3: main — one CTA per (b,d); GEMM-like 16q x 1000l with binning epilogue
// smem layout (floats):
//   qs   [300][16]              4800
//   ds   [2][8][1008]          16128   (doc tile, transposed [e][l], double buffered)
//   idxs [1000] (int)           1000
//   invnd[1000]                 1000
//   tbl  [16*5]                   80
//   red  [256]                   256
// total 23264 floats = 93056 B
#define SMEM_FLOATS 23264

__global__ __launch_bounds__(256) void k_main(const int* __restrict__ docs,
                                              const float* __restrict__ emb,
                                              float* __restrict__ out) {
    extern __shared__ float sm[];
    float* qs    = sm;             // 4800
    float* ds    = sm + 4800;      // 16128
    int*   idxs  = (int*)(sm + 20928);
    float* invnd = sm + 21928;
    float* tbl   = sm + 22928;
    float* red   = sm + 23008;

    const int t = threadIdx.x;
    const int bb = blockIdx.x / DD, dd = blockIdx.x % DD;

    // --- prologue loads ---
    const int* dix = docs + (bb * DD + dd) * LL;
    for (int i = t; i < LL; i += 256) idxs[i] = dix[i];
    {
        const float4* src = (const float4*)(g_qn + bb * (EMSIZE * QQ));
        float4* dst = (float4*)qs;
        for (int i = t; i < (EMSIZE * QQ) / 4; i += 256) dst[i] = src[i];
    }
    if (t < QQ * NBINS) tbl[t] = g_tbl[bb * QQ * NBINS + t];
    __syncthreads();
    for (int i = t; i < LL; i += 256) invnd[i] = g_invnorm[idxs[i]];

    // --- accumulators: 16 queries (8 f32x2 pairs) x 4 doc terms per thread ---
    ull acc[8][4];
#pragma unroll
    for (int i = 0; i < 8; i++)
#pragma unroll
        for (int m = 0; m < 4; m++) acc[i][m] = 0ull;

    const int l0 = t * 4;
    const bool active = (t < 250);

    // chunk staging: 38 chunks of 8 e-columns (last chunk: 4 cols).
    // items: 0..999 -> half 0 (cols 0..3), 1000..1999 -> half 1 (cols 4..7)
    float4 stg[8];
    auto ld = [&](int c) {
        const int e0 = c * 8;
        const bool full = (c < 37);
#pragma unroll
        for (int j = 0; j < 8; j++) {
            int item = t + j * 256;
            bool v = (item < 2000) && (full || item < 1000);
            if (v) {
                int hf = (item >= 1000);
                int row = item - hf * 1000;
                stg[j] = *(const float4*)(emb + (size_t)idxs[row] * EMSIZE + e0 + hf * 4);
            }
        }
    };
    auto st = [&](int c, int buf) {
        const bool full = (c < 37);
        float* dbase = ds + buf * 8064;
#pragma unroll
        for (int j = 0; j < 8; j++) {
            int item = t + j * 256;
            bool v = (item < 2000) && (full || item < 1000);
            if (v) {
                int hf = (item >= 1000);
                int row = item - hf * 1000;
                float* p = dbase + hf * 4032 + row;  // hf*4 rows of 1008
                p[0]    = stg[j].x;
                p[1008] = stg[j].y;
                p[2016] = stg[j].z;
                p[3024] = stg[j].w;
            }
        }
    };

    ld(0);
    st(0, 0);
    __syncthreads();

    int buf = 0;
    for (int c = 0; c < 38; c++) {
        if (c + 1 < 38) ld(c + 1);
        if (active) {
            const float* dsb  = ds + buf * 8064 + l0;
            const float* qrow = qs + c * 8 * QQ;
            if (c < 37) {
#pragma unroll
                for (int k = 0; k < 8; k++) {
                    float4 bq = *(const float4*)(dsb + k * 1008);
                    const ull* ar = (const ull*)(qrow + k * QQ);
                    ull bx = dup2(bq.x), by = dup2(bq.y), bz = dup2(bq.z), bw = dup2(bq.w);
#pragma unroll
                    for (int qp = 0; qp < 8; qp++) {
                        ull a = ar[qp];
                        acc[qp][0] = fma2(a, bx, acc[qp][0]);
                        acc[qp][1] = fma2(a, by, acc[qp][1]);
                        acc[qp][2] = fma2(a, bz, acc[qp][2]);
                        acc[qp][3] = fma2(a, bw, acc[qp][3]);
                    }
                }
            } else {
#pragma unroll
                for (int k = 0; k < 4; k++) {
                    float4 bq = *(const float4*)(dsb + k * 1008);
                    const ull* ar = (const ull*)(qrow + k * QQ);
                    ull bx = dup2(bq.x), by = dup2(bq.y), bz = dup2(bq.z), bw = dup2(bq.w);
#pragma unroll
                    for (int qp = 0; qp < 8; qp++) {
                        ull a = ar[qp];
                        acc[qp][0] = fma2(a, bx, acc[qp][0]);
                        acc[qp][1] = fma2(a, by, acc[qp][1]);
                        acc[qp][2] = fma2(a, bz, acc[qp][2]);
                        acc[qp][3] = fma2(a, bw, acc[qp][3]);
                    }
                }
            }
        }
        if (c + 1 < 38) st(c + 1, buf ^ 1);
        __syncthreads();
        buf ^= 1;
    }

    // --- epilogue: bin each cosine, accumulate tw*w1[bin] ---
    float s = 0.0f;
    if (active) {
#pragma unroll
        for (int m = 0; m < 4; m++) {
            float inl = invnd[l0 + m];
#pragma unroll
            for (int qp = 0; qp < 8; qp++) {
                float lo, hi;
                unpack2(acc[qp][m], lo, hi);
                s += contrib(lo * inl, tbl + (2 * qp) * NBINS);
                s += contrib(hi * inl, tbl + (2 * qp + 1) * NBINS);
            }
        }
    }
    red[t] = s;
    __syncthreads();
#pragma unroll
    for (int o = 128; o > 0; o >>= 1) {
        if (t < o) red[t] += red[t + o];
        __syncthreads();
    }
    if (t == 0) out[bb * DD + dd] = g_c0[bb] + g_c1 * red[0];
}

// ---------------- launch ----------------
extern "C" void kernel_launch(void* const* d_in, const int* in_sizes, int n_in,
                              void* d_out, int out_size) {
    const int*   queries = (const int*)d_in[0];
    const int*   docs    = (const int*)d_in[1];
    const float* emb     = (const float*)d_in[2];
    const float* gate_w  = (const float*)d_in[3];
    const float* gate_b  = (const float*)d_in[4];
    const float* w1      = (const float*)d_in[5];
    const float* b1      = (const float*)d_in[6];
    const float* w2      = (const float*)d_in[7];
    const float* b2      = (const float*)d_in[8];
    const float* ow      = (const float*)d_in[9];
    const float* ob      = (const float*)d_in[10];
    float* out = (float*)d_out;

    cudaFuncSetAttribute(k_main, cudaFuncAttributeMaxDynamicSharedMemorySize,
                         SMEM_FLOATS * (int)sizeof(float));

    // K0: vocab inverse norms (warp per row)
    k_vocab_norms<<<(VOCABSZ * 32 + 255) / 256, 256>>>(emb);
    // K1: query prep (warp per (b,q))
    k_query_prep<<<(BB * QQ * 32 + 255) / 256, 256>>>(queries, emb, gate_w, gate_b);
    // K2: softmax + constant folding
    k_softmax<<<1, BB * QQ>>>(w1, b1, w2, b2, ow, ob);
    // K3: main scoring kernel, one CTA per (b,d)
    k_main<<<BB * DD, 256, SMEM_FLOATS * (int)sizeof(float)>>>(docs, emb, out);
}

// round 2
// speedup vs baseline: 1.0183x; 1.0183x over previous
#include <cuda_runtime.h>

#define VOCABSZ 50000
#define EMSIZE  300
#define NBINS   5
#define BB      32
#define QQ      16
#define DD      10
#define LL      1000
#define CHUNKS  75     // e-chunks of 4: 75*4 = 300

typedef unsigned long long ull;

// ---------------- device scratch (no allocations allowed) ----------------
__device__ float g_invnorm[VOCABSZ];
__device__ float g_qn[BB * EMSIZE * QQ];   // [b][e][q], pre-normalized query embeddings
__device__ float g_tbl[BB * QQ * NBINS];   // tw[b,q] * w1[n]
__device__ float g_logits[BB * QQ];
__device__ float g_c0[BB];
__device__ float g_c1;

// ---------------- helpers ----------------
__device__ __forceinline__ ull fma2(ull a, ull b, ull c) {
    ull d;
    asm("fma.rn.f32x2 %0, %1, %2, %3;" : "=l"(d) : "l"(a), "l"(b), "l"(c));
    return d;
}
__device__ __forceinline__ ull dup2(float x) {
    ull d;
    asm("mov.b64 %0, {%1, %1};" : "=l"(d) : "r"(__float_as_uint(x)));
    return d;
}
__device__ __forceinline__ void unpack2(ull p, float& lo, float& hi) {
    unsigned a, b;
    asm("mov.b64 {%0, %1}, %2;" : "=r"(a), "=r"(b) : "l"(p));
    lo = __uint_as_float(a);
    hi = __uint_as_float(b);
}
__device__ __forceinline__ float warp_sum(float v) {
#pragma unroll
    for (int o = 16; o > 0; o >>= 1) v += __shfl_xor_sync(0xffffffffu, v, o);
    return v;
}
__device__ __forceinline__ void cp16(unsigned dst, const void* src) {
    asm volatile("cp.async.ca.shared.global [%0], [%1], 16;\n" :: "r"(dst), "l"(src));
}
__device__ __forceinline__ void cp_commit() {
    asm volatile("cp.async.commit_group;\n" ::: "memory");
}
__device__ __forceinline__ void cp_wait0() {
    asm volatile("cp.async.wait_group 0;\n" ::: "memory");
}

// bin semantics from reference: [-1,-.5) [-0.5,0) [0,.5) [.5,1) and {==1.0};
// out-of-range values fall into no bin (contribute 0).
__device__ __forceinline__ float contrib(float v, const float* t5) {
    if (v < -1.0f) return 0.0f;
    if (v < -0.5f) return t5[0];
    if (v <  0.0f) return t5[1];
    if (v <  0.5f) return t5[2];
    if (v <  1.0f) return t5[3];
    return (v == 1.0f) ? t5[4] : 0.0f;
}

// ---------------- K0: per-vocab inverse norms ----------------
__global__ void k_vocab_norms(const float* __restrict__ emb) {
    int w = (blockIdx.x * blockDim.x + threadIdx.x) >> 5;
    int lane = threadIdx.x & 31;
    if (w >= VOCABSZ) return;
    const float* row = emb + (size_t)w * EMSIZE;
    float s = 0.0f;
    for (int e = lane; e < EMSIZE; e += 32) {
        float v = row[e];
        s += v * v;
    }
    s = warp_sum(s);
    if (lane == 0) g_invnorm[w] = 1.0f / sqrtf(s);
}

// ---------------- K1: gather + normalize query embeddings, gate logits ----------------
__global__ void k_query_prep(const int* __restrict__ queries, const float* __restrict__ emb,
                             const float* __restrict__ gate_w, const float* __restrict__ gate_b) {
    int w = (blockIdx.x * blockDim.x + threadIdx.x) >> 5;  // (b,q) index 0..511
    int lane = threadIdx.x & 31;
    if (w >= BB * QQ) return;
    int b = w >> 4, q = w & 15;
    int tok = queries[w];
    const float* row = emb + (size_t)tok * EMSIZE;
    float vv[10];
    float s = 0.0f, g = 0.0f;
    int n = 0;
    for (int e = lane; e < EMSIZE; e += 32) {
        float v = row[e];
        vv[n++] = v;
        s += v * v;
        g += v * gate_w[e];
    }
    s = warp_sum(s);
    g = warp_sum(g);
    float invn = 1.0f / sqrtf(s);
    if (lane == 0) g_logits[w] = g + gate_b[0];
    n = 0;
    for (int e = lane; e < EMSIZE; e += 32) {
        g_qn[b * (EMSIZE * QQ) + e * QQ + q] = vv[n++] * invn;  // transposed [e][q]
    }
}

// ---------------- K2: softmax over query terms + fused scalar constants ----------------
__global__ void k_softmax(const float* __restrict__ w1, const float* __restrict__ b1,
                          const float* __restrict__ w2, const float* __restrict__ b2,
                          const float* __restrict__ ow, const float* __restrict__ ob) {
    int t = threadIdx.x;  // 512 threads: b = t/16, q = t%16
    int b = t >> 4, q = t & 15;
    float logit = g_logits[t];
    float m = logit;
#pragma unroll
    for (int o = 8; o > 0; o >>= 1) m = fmaxf(m, __shfl_xor_sync(0xffffffffu, m, o, 16));
    float e = expf(logit - m);
    float sum = e;
#pragma unroll
    for (int o = 8; o > 0; o >>= 1) sum += __shfl_xor_sync(0xffffffffu, sum, o, 16);
    float tw = e / sum;
    float tws = tw;
#pragma unroll
    for (int o = 8; o > 0; o >>= 1) tws += __shfl_xor_sync(0xffffffffu, tws, o, 16);
#pragma unroll
    for (int n = 0; n < NBINS; n++) g_tbl[(b * QQ + q) * NBINS + n] = tw * w1[n];
    if (q == 0) g_c0[b] = ob[0] + ow[0] * (w2[0] * b1[0] + b2[0]) * tws;
    if (t == 0) g_c1 = ow[0] * w2[0];
}

// ---------------- K3: main — one CTA per (b,d), 2 CTAs/SM
// smem layout (floats):
//   qs   [300][16]            4800
//   ds   [2][1000][4]         8000   (doc tile, [l][4e] rows, double buffered, cp.async dst)
//   idxs [1000] (int)         1000
//   invnd[1000]               1000
//   tbl  [16*5]                 80
//   red  [8]                     8
// total 14888 floats = 59552 B  -> 2 CTAs/SM = 119104 B
#define SMEM_FLOATS 14888

__global__ __launch_bounds__(256, 2) void k_main(const int* __restrict__ docs,
                                                 const float* __restrict__ emb,
                                                 float* __restrict__ out) {
    extern __shared__ float sm[];
    float* qs    = sm;              // 4800
    float* ds    = sm + 4800;       // 8000
    int*   idxs  = (int*)(sm + 12800);
    float* invnd = sm + 13800;
    float* tbl   = sm + 14800;
    float* red   = sm + 14880;

    const int t = threadIdx.x;
    const int bb = blockIdx.x / DD, dd = blockIdx.x % DD;

    // --- prologue loads ---
    const int* dix = docs + (bb * DD + dd) * LL;
    for (int i = t; i < LL; i += 256) idxs[i] = dix[i];
    {
        const float4* src = (const float4*)(g_qn + bb * (EMSIZE * QQ));
        float4* dst = (float4*)qs;
        for (int i = t; i < (EMSIZE * QQ) / 4; i += 256) dst[i] = src[i];
    }
    if (t < QQ * NBINS) tbl[t] = g_tbl[bb * QQ * NBINS + t];
    __syncthreads();
    for (int i = t; i < LL; i += 256) invnd[i] = g_invnorm[idxs[i]];

    // --- cp.async doc-tile loader: e-chunk of 4 floats per l, [l][4] rows ---
    auto issue = [&](int c, int buf) {
        const int e0 = c * 4;
        float* db = ds + buf * 4000;
#pragma unroll
        for (int j = 0; j < 4; j++) {
            int row = t + j * 256;
            if (row < LL) {
                unsigned dstp = (unsigned)__cvta_generic_to_shared(db + row * 4);
                cp16(dstp, emb + (size_t)idxs[row] * EMSIZE + e0);
            }
        }
    };

    // --- accumulators: 16 queries (8 f32x2 pairs) x 4 doc terms per thread ---
    ull acc[8][4];
#pragma unroll
    for (int i = 0; i < 8; i++)
#pragma unroll
        for (int m = 0; m < 4; m++) acc[i][m] = 0ull;

    const bool active = (t < 250);

    issue(0, 0);
    cp_commit();
    cp_wait0();
    __syncthreads();

    int buf = 0;
    for (int c = 0; c < CHUNKS; c++) {
        if (c + 1 < CHUNKS) {
            issue(c + 1, buf ^ 1);
            cp_commit();
        }
        if (active) {
            const float* db = ds + buf * 4000;
            // thread t owns doc terms l = t, t+250, t+500, t+750 (conflict-free LDS.128)
            float4 d0 = *(const float4*)(db + (t       ) * 4);
            float4 d1 = *(const float4*)(db + (t +  250) * 4);
            float4 d2 = *(const float4*)(db + (t +  500) * 4);
            float4 d3 = *(const float4*)(db + (t +  750) * 4);
            const ull* qr = (const ull*)(qs + c * 4 * QQ);
#pragma unroll
            for (int e = 0; e < 4; e++) {
                ull q[8];
#pragma unroll
                for (int qp = 0; qp < 8; qp++) q[qp] = qr[e * 8 + qp];
                ull b0 = dup2(((const float*)&d0)[e]);
                ull b1 = dup2(((const float*)&d1)[e]);
                ull b2 = dup2(((const float*)&d2)[e]);
                ull b3 = dup2(((const float*)&d3)[e]);
#pragma unroll
                for (int qp = 0; qp < 8; qp++) {
                    acc[qp][0] = fma2(q[qp], b0, acc[qp][0]);
                    acc[qp][1] = fma2(q[qp], b1, acc[qp][1]);
                    acc[qp][2] = fma2(q[qp], b2, acc[qp][2]);
                    acc[qp][3] = fma2(q[qp], b3, acc[qp][3]);
                }
            }
        }
        if (c + 1 < CHUNKS) cp_wait0();
        __syncthreads();
        buf ^= 1;
    }

    // --- epilogue: bin each cosine, accumulate tw*w1[bin] ---
    float s = 0.0f;
    if (active) {
#pragma unroll
        for (int m = 0; m < 4; m++) {
            float inl = invnd[t + 250 * m];
#pragma unroll
            for (int qp = 0; qp < 8; qp++) {
                float lo, hi;
                unpack2(acc[qp][m], lo, hi);
                s += contrib(lo * inl, tbl + (2 * qp) * NBINS);
                s += contrib(hi * inl, tbl + (2 * qp + 1) * NBINS);
            }
        }
    }
    s = warp_sum(s);
    if ((t & 31) == 0) red[t >> 5] = s;
    __syncthreads();
    if (t == 0) {
        float tot = 0.0f;
#pragma unroll
        for (int w = 0; w < 8; w++) tot += red[w];
        out[bb * DD + dd] = g_c0[bb] + g_c1 * tot;
    }
}

// ---------------- launch ----------------
extern "C" void kernel_launch(void* const* d_in, const int* in_sizes, int n_in,
                              void* d_out, int out_size) {
    const int*   queries = (const int*)d_in[0];
    const int*   docs    = (const int*)d_in[1];
    const float* emb     = (const float*)d_in[2];
    const float* gate_w  = (const float*)d_in[3];
    const float* gate_b  = (const float*)d_in[4];
    const float* w1      = (const float*)d_in[5];
    const float* b1      = (const float*)d_in[6];
    const float* w2      = (const float*)d_in[7];
    const float* b2      = (const float*)d_in[8];
    const float* ow      = (const float*)d_in[9];
    const float* ob      = (const float*)d_in[10];
    float* out = (float*)d_out;

    cudaFuncSetAttribute(k_main, cudaFuncAttributeMaxDynamicSharedMemorySize,
                         SMEM_FLOATS * (int)sizeof(float));

    // K0: vocab inverse norms (warp per row)
    k_vocab_norms<<<(VOCABSZ * 32 + 255) / 256, 256>>>(emb);
    // K1: query prep (warp per (b,q))
    k_query_prep<<<(BB * QQ * 32 + 255) / 256, 256>>>(queries, emb, gate_w, gate_b);
    // K2: softmax + constant folding
    k_softmax<<<1, BB * QQ>>>(w1, b1, w2, b2, ow, ob);
    // K3: main scoring kernel, one CTA per (b,d)
    k_main<<<BB * DD, 256, SMEM_FLOATS * (int)sizeof(float)>>>(docs, emb, out);
}

// round 3
// speedup vs baseline: 1.0203x; 1.0020x over previous
#include <cuda_runtime.h>

#define VOCABSZ 50000
#define EMSIZE  300
#define NBINS   5
#define BB      32
#define QQ      16
#define DD      10
#define LL      1000
#define CHUNKS  75     // e-chunks of 4: 75*4 = 300

typedef unsigned long long ull;

// ---------------- device scratch (no allocations allowed) ----------------
__device__ float g_invnorm[VOCABSZ];
__device__ float g_qn[BB * EMSIZE * QQ];   // [b][e][q], pre-normalized query embeddings
__device__ float g_tbl[BB * QQ * NBINS];   // tw[b,q] * w1[n]
__device__ float g_logits[BB * QQ];
__device__ float g_c0[BB];
__device__ float g_c1;

// ---------------- helpers ----------------
__device__ __forceinline__ ull fma2(ull a, ull b, ull c) {
    ull d;
    asm("fma.rn.f32x2 %0, %1, %2, %3;" : "=l"(d) : "l"(a), "l"(b), "l"(c));
    return d;
}
__device__ __forceinline__ ull dup2(float x) {
    ull d;
    asm("mov.b64 %0, {%1, %1};" : "=l"(d) : "r"(__float_as_uint(x)));
    return d;
}
__device__ __forceinline__ void unpack2(ull p, float& lo, float& hi) {
    unsigned a, b;
    asm("mov.b64 {%0, %1}, %2;" : "=r"(a), "=r"(b) : "l"(p));
    lo = __uint_as_float(a);
    hi = __uint_as_float(b);
}
__device__ __forceinline__ float warp_sum(float v) {
#pragma unroll
    for (int o = 16; o > 0; o >>= 1) v += __shfl_xor_sync(0xffffffffu, v, o);
    return v;
}
__device__ __forceinline__ void cp16(unsigned dst, const void* src) {
    asm volatile("cp.async.ca.shared.global [%0], [%1], 16;\n" :: "r"(dst), "l"(src));
}
__device__ __forceinline__ void cp_commit() {
    asm volatile("cp.async.commit_group;\n" ::: "memory");
}
__device__ __forceinline__ void cp_wait0() {
    asm volatile("cp.async.wait_group 0;\n" ::: "memory");
}

// bin semantics from reference: [-1,-.5) [-0.5,0) [0,.5) [.5,1) and {==1.0};
// out-of-range values fall into no bin (contribute 0).
__device__ __forceinline__ float contrib(float v, const float* t5) {
    if (v < -1.0f) return 0.0f;
    if (v < -0.5f) return t5[0];
    if (v <  0.0f) return t5[1];
    if (v <  0.5f) return t5[2];
    if (v <  1.0f) return t5[3];
    return (v == 1.0f) ? t5[4] : 0.0f;
}

// ---------------- K0: per-vocab inverse norms ----------------
__global__ void k_vocab_norms(const float* __restrict__ emb) {
    int w = (blockIdx.x * blockDim.x + threadIdx.x) >> 5;
    int lane = threadIdx.x & 31;
    if (w >= VOCABSZ) return;
    const float* row = emb + (size_t)w * EMSIZE;
    float s = 0.0f;
    for (int e = lane; e < EMSIZE; e += 32) {
        float v = row[e];
        s += v * v;
    }
    s = warp_sum(s);
    if (lane == 0) g_invnorm[w] = 1.0f / sqrtf(s);
}

// ---------------- K1: gather + normalize query embeddings, gate logits ----------------
__global__ void k_query_prep(const int* __restrict__ queries, const float* __restrict__ emb,
                             const float* __restrict__ gate_w, const float* __restrict__ gate_b) {
    int w = (blockIdx.x * blockDim.x + threadIdx.x) >> 5;  // (b,q) index 0..511
    int lane = threadIdx.x & 31;
    if (w >= BB * QQ) return;
    int b = w >> 4, q = w & 15;
    int tok = queries[w];
    const float* row = emb + (size_t)tok * EMSIZE;
    float vv[10];
    float s = 0.0f, g = 0.0f;
    int n = 0;
    for (int e = lane; e < EMSIZE; e += 32) {
        float v = row[e];
        vv[n++] = v;
        s += v * v;
        g += v * gate_w[e];
    }
    s = warp_sum(s);
    g = warp_sum(g);
    float invn = 1.0f / sqrtf(s);
    if (lane == 0) g_logits[w] = g + gate_b[0];
    n = 0;
    for (int e = lane; e < EMSIZE; e += 32) {
        g_qn[b * (EMSIZE * QQ) + e * QQ + q] = vv[n++] * invn;  // transposed [e][q]
    }
}

// ---------------- K2: softmax over query terms + fused scalar constants ----------------
__global__ void k_softmax(const float* __restrict__ w1, const float* __restrict__ b1,
                          const float* __restrict__ w2, const float* __restrict__ b2,
                          const float* __restrict__ ow, const float* __restrict__ ob) {
    int t = threadIdx.x;  // 512 threads: b = t/16, q = t%16
    int b = t >> 4, q = t & 15;
    float logit = g_logits[t];
    float m = logit;
#pragma unroll
    for (int o = 8; o > 0; o >>= 1) m = fmaxf(m, __shfl_xor_sync(0xffffffffu, m, o, 16));
    float e = expf(logit - m);
    float sum = e;
#pragma unroll
    for (int o = 8; o > 0; o >>= 1) sum += __shfl_xor_sync(0xffffffffu, sum, o, 16);
    float tw = e / sum;
    float tws = tw;
#pragma unroll
    for (int o = 8; o > 0; o >>= 1) tws += __shfl_xor_sync(0xffffffffu, tws, o, 16);
#pragma unroll
    for (int n = 0; n < NBINS; n++) g_tbl[(b * QQ + q) * NBINS + n] = tw * w1[n];
    if (q == 0) g_c0[b] = ob[0] + ow[0] * (w2[0] * b1[0] + b2[0]) * tws;
    if (t == 0) g_c1 = ow[0] * w2[0];
}

// ---------------- K3: main — one CTA per (b,d), 2 CTAs/SM
// smem layout (floats):
//   qs   [300][16]            4800
//   ds   [2][1000][4]         8000   (doc tile, [l][4e] rows, double buffered, cp.async dst)
//   idxs [1000] (int)         1000
//   invnd[1000]               1000
//   tbl  [16*5]                 80
//   red  [8]                     8
// total 14888 floats = 59552 B  -> 2 CTAs/SM = 119104 B
#define SMEM_FLOATS 14888

__global__ __launch_bounds__(256, 2) void k_main(const int* __restrict__ docs,
                                                 const float* __restrict__ emb,
                                                 float* __restrict__ out) {
    extern __shared__ float sm[];
    float* qs    = sm;              // 4800
    float* ds    = sm + 4800;       // 8000
    int*   idxs  = (int*)(sm + 12800);
    float* invnd = sm + 13800;
    float* tbl   = sm + 14800;
    float* red   = sm + 14880;

    const int t = threadIdx.x;
    const int bb = blockIdx.x / DD, dd = blockIdx.x % DD;

    // --- prologue loads ---
    const int* dix = docs + (bb * DD + dd) * LL;
    for (int i = t; i < LL; i += 256) idxs[i] = dix[i];
    {
        const float4* src = (const float4*)(g_qn + bb * (EMSIZE * QQ));
        float4* dst = (float4*)qs;
        for (int i = t; i < (EMSIZE * QQ) / 4; i += 256) dst[i] = src[i];
    }
    if (t < QQ * NBINS) tbl[t] = g_tbl[bb * QQ * NBINS + t];
    __syncthreads();
    for (int i = t; i < LL; i += 256) invnd[i] = g_invnorm[idxs[i]];

    // --- cp.async doc-tile loader: e-chunk of 4 floats per l, [l][4] rows ---
    auto issue = [&](int c, int buf) {
        const int e0 = c * 4;
        float* db = ds + buf * 4000;
#pragma unroll
        for (int j = 0; j < 4; j++) {
            int row = t + j * 256;
            if (row < LL) {
                unsigned dstp = (unsigned)__cvta_generic_to_shared(db + row * 4);
                cp16(dstp, emb + (size_t)idxs[row] * EMSIZE + e0);
            }
        }
    };

    // --- accumulators: 16 queries (8 f32x2 pairs) x 4 doc terms per thread ---
    ull acc[8][4];
#pragma unroll
    for (int i = 0; i < 8; i++)
#pragma unroll
        for (int m = 0; m < 4; m++) acc[i][m] = 0ull;

    const bool active = (t < 250);

    issue(0, 0);
    cp_commit();
    cp_wait0();
    __syncthreads();

    int buf = 0;
    for (int c = 0; c < CHUNKS; c++) {
        if (c + 1 < CHUNKS) {
            issue(c + 1, buf ^ 1);
            cp_commit();
        }
        if (active) {
            const float* db = ds + buf * 4000;
            // thread t owns doc terms l = t, t+250, t+500, t+750 (conflict-free LDS.128)
            float4 d0 = *(const float4*)(db + (t       ) * 4);
            float4 d1 = *(const float4*)(db + (t +  250) * 4);
            float4 d2 = *(const float4*)(db + (t +  500) * 4);
            float4 d3 = *(const float4*)(db + (t +  750) * 4);
            const ull* qr = (const ull*)(qs + c * 4 * QQ);
#pragma unroll
            for (int e = 0; e < 4; e++) {
                ull q[8];
#pragma unroll
                for (int qp = 0; qp < 8; qp++) q[qp] = qr[e * 8 + qp];
                ull b0 = dup2(((const float*)&d0)[e]);
                ull b1 = dup2(((const float*)&d1)[e]);
                ull b2 = dup2(((const float*)&d2)[e]);
                ull b3 = dup2(((const float*)&d3)[e]);
#pragma unroll
                for (int qp = 0; qp < 8; qp++) {
                    acc[qp][0] = fma2(q[qp], b0, acc[qp][0]);
                    acc[qp][1] = fma2(q[qp], b1, acc[qp][1]);
                    acc[qp][2] = fma2(q[qp], b2, acc[qp][2]);
                    acc[qp][3] = fma2(q[qp], b3, acc[qp][3]);
                }
            }
        }
        if (c + 1 < CHUNKS) cp_wait0();
        __syncthreads();
        buf ^= 1;
    }

    // --- epilogue: bin each cosine, accumulate tw*w1[bin] ---
    float s = 0.0f;
    if (active) {
#pragma unroll
        for (int m = 0; m < 4; m++) {
            float inl = invnd[t + 250 * m];
#pragma unroll
            for (int qp = 0; qp < 8; qp++) {
                float lo, hi;
                unpack2(acc[qp][m], lo, hi);
                s += contrib(lo * inl, tbl + (2 * qp) * NBINS);
                s += contrib(hi * inl, tbl + (2 * qp + 1) * NBINS);
            }
        }
    }
    s = warp_sum(s);
    if ((t & 31) == 0) red[t >> 5] = s;
    __syncthreads();
    if (t == 0) {
        float tot = 0.0f;
#pragma unroll
        for (int w = 0; w < 8; w++) tot += red[w];
        out[bb * DD + dd] = g_c0[bb] + g_c1 * tot;
    }
}

// ---------------- launch ----------------
extern "C" void kernel_launch(void* const* d_in, const int* in_sizes, int n_in,
                              void* d_out, int out_size) {
    const int*   queries = (const int*)d_in[0];
    const int*   docs    = (const int*)d_in[1];
    const float* emb     = (const float*)d_in[2];
    const float* gate_w  = (const float*)d_in[3];
    const float* gate_b  = (const float*)d_in[4];
    const float* w1      = (const float*)d_in[5];
    const float* b1      = (const float*)d_in[6];
    const float* w2      = (const float*)d_in[7];
    const float* b2      = (const float*)d_in[8];
    const float* ow      = (const float*)d_in[9];
    const float* ob      = (const float*)d_in[10];
    float* out = (float*)d_out;

    cudaFuncSetAttribute(k_main, cudaFuncAttributeMaxDynamicSharedMemorySize,
                         SMEM_FLOATS * (int)sizeof(float));

    // K0: vocab inverse norms (warp per row)
    k_vocab_norms<<<(VOCABSZ * 32 + 255) / 256, 256>>>(emb);
    // K1: query prep (warp per (b,q))
    k_query_prep<<<(BB * QQ * 32 + 255) / 256, 256>>>(queries, emb, gate_w, gate_b);
    // K2: softmax + constant folding
    k_softmax<<<1, BB * QQ>>>(w1, b1, w2, b2, ow, ob);
    // K3: main scoring kernel, one CTA per (b,d)
    k_main<<<BB * DD, 256, SMEM_FLOATS * (int)sizeof(float)>>>(docs, emb, out);
}